// round 12
// baseline (speedup 1.0000x reference)
#include <cuda_runtime.h>
#include <math.h>
#include <stdint.h>

#define DM 1024
#define NH 16
#define HD 64
#define NB 8
#define LQ 512
#define MROWS 4096          // NB*LQ
#define ATT_SCALE 0.125f    // 64^-0.5
#define EPS 1e-5f
#define ROPE_C (-0.28782313662425576f)   // -ln(10000)/32

// ---------------- scratch (static device globals; no allocation) -------------
__device__ float g_qin[MROWS * DM];
__device__ float g_kvin[MROWS * DM];
__device__ float g_q[MROWS * DM];
__device__ float g_k[MROWS * DM];
__device__ float g_v[MROWS * DM];
__device__ float g_att[MROWS * DM];
__device__ float g_proj[MROWS * DM];
__device__ float g_bias[LQ * LQ];

// ---------------- helpers ----------------------------------------------------
__device__ __forceinline__ float rtf32(float x) {
    uint32_t r;
    asm("cvt.rna.tf32.f32 %0, %1;" : "=r"(r) : "f"(x));
    return __uint_as_float(r);
}
__device__ __forceinline__ uint32_t smem_u32(const void* p) {
    uint32_t a;
    asm("{ .reg .u64 t; cvta.to.shared.u64 t, %1; cvt.u32.u64 %0, t; }" : "=r"(a) : "l"(p));
    return a;
}
__device__ __forceinline__ void cpasync16(uint32_t s, const void* g) {
    asm volatile("cp.async.cg.shared.global [%0], [%1], 16;" :: "r"(s), "l"(g));
}
#define CP_COMMIT() asm volatile("cp.async.commit_group;" ::: "memory")

__device__ __forceinline__ void mma8(float* d, const uint32_t* a, const uint32_t* b) {
    asm volatile(
        "mma.sync.aligned.m16n8k8.row.col.f32.tf32.tf32.f32 "
        "{%0,%1,%2,%3}, {%4,%5,%6,%7}, {%8,%9}, {%0,%1,%2,%3};"
        : "+f"(d[0]), "+f"(d[1]), "+f"(d[2]), "+f"(d[3])
        : "r"(a[0]), "r"(a[1]), "r"(a[2]), "r"(a[3]), "r"(b[0]), "r"(b[1]));
}

// ======================= TF32 mma.sync GEMM core =============================
// C[M,N] = A[M,K=1024] * W[N,K=1024]^T ; CTA tile 128(M) x 256(N), BK=32.
// 16 warps (512 thr), 4(M) x 4(N) warp grid, warp tile 32x64, mma m16n8k8.
#define GBM 128
#define GBN 256
#define GBK 32
#define ASTR 36                          // smem row stride in floats (bank-CF)
#define A_SMF (GBM * ASTR)               // 4608 floats
#define B_SMF (GBN * ASTR)               // 9216 floats
#define STG_F (A_SMF + B_SMF)            // 13824 floats
#define STG_B (STG_F * 4)                // 55296 bytes
#define NSTG 3
#define NCHK (DM / GBK)                  // 32
#define GEMM_SMEM (NSTG * STG_B)         // 165888 bytes
#define GT 512

// Mainloop shared by all GEMM kernels: fills acc[2][8][4].
__device__ __forceinline__ void gemm_mainloop(const float* __restrict__ A,
                                              const float* __restrict__ W,
                                              float* smf, uint32_t sbase,
                                              int brow, int bcol,
                                              float acc[2][8][4]) {
    int tid = threadIdx.x;
    int wid = tid >> 5, lane = tid & 31;
    int gid = lane >> 2, tig = lane & 3;
    int wm = wid >> 2, wn = wid & 3;

    const char* Arow = (const char*)(A + (size_t)brow * DM);
    const char* Wrow = (const char*)(W + (size_t)bcol * DM);

    auto load_chunk = [&](int c, int st) {
        uint32_t sA = sbase + st * STG_B;
        uint32_t sB = sA + A_SMF * 4;
        const char* Ag = Arow + (size_t)c * GBK * 4;
        const char* Bg = Wrow + (size_t)c * GBK * 4;
#pragma unroll
        for (int j = 0; j < 2; j++) {          // A: 1024 granules / 512 thr
            int gi = tid + j * GT;
            int r = gi >> 3, g = gi & 7;
            cpasync16(sA + r * 144 + g * 16, Ag + (size_t)r * (DM * 4) + g * 16);
        }
#pragma unroll
        for (int j = 0; j < 4; j++) {          // B: 2048 granules / 512 thr
            int gi = tid + j * GT;
            int r = gi >> 3, g = gi & 7;
            cpasync16(sB + r * 144 + g * 16, Bg + (size_t)r * (DM * 4) + g * 16);
        }
        CP_COMMIT();
    };

    load_chunk(0, 0);
    load_chunk(1, 1);

    for (int c = 0; c < NCHK; c++) {
        int st = c % NSTG;
        if (c + 2 < NCHK) load_chunk(c + 2, (c + 2) % NSTG);
        if (c < NCHK - 2)       asm volatile("cp.async.wait_group 2;" ::: "memory");
        else if (c == NCHK - 2) asm volatile("cp.async.wait_group 1;" ::: "memory");
        else                    asm volatile("cp.async.wait_group 0;" ::: "memory");
        __syncthreads();

        const float* sA = smf + st * STG_F;
        const float* sB = sA + A_SMF;
#pragma unroll
        for (int ks = 0; ks < 4; ks++) {
            int col = 8 * ks + tig;
            uint32_t af[2][4];
#pragma unroll
            for (int i = 0; i < 2; i++) {
                int m = wm * 32 + 16 * i + gid;
                af[i][0] = __float_as_uint(sA[m * ASTR + col]);
                af[i][1] = __float_as_uint(sA[(m + 8) * ASTR + col]);
                af[i][2] = __float_as_uint(sA[m * ASTR + col + 4]);
                af[i][3] = __float_as_uint(sA[(m + 8) * ASTR + col + 4]);
            }
            uint32_t bf[8][2];
#pragma unroll
            for (int j = 0; j < 8; j++) {
                int n = wn * 64 + 8 * j + gid;
                bf[j][0] = __float_as_uint(sB[n * ASTR + col]);
                bf[j][1] = __float_as_uint(sB[n * ASTR + col + 4]);
            }
#pragma unroll
            for (int i = 0; i < 2; i++)
#pragma unroll
                for (int j = 0; j < 8; j++) mma8(acc[i][j], af[i], bf[j]);
        }
        __syncthreads();
    }
}

// ---- fused QKV GEMM + RoPE epilogue -----------------------------------------
// z = blockIdx.z: 0 -> Q (rope), 1 -> K (rope), 2 -> V (plain).
__global__ __launch_bounds__(GT, 1) void qkv_mma(const float* __restrict__ Wqkv) {
    extern __shared__ float smf[];
    uint32_t sbase = smem_u32(smf);
    int z = blockIdx.z;
    int brow = blockIdx.y * GBM;
    int bcol = blockIdx.x * GBN;

    const float* A = (z == 0) ? g_qin : g_kvin;
    const float* W = Wqkv + (size_t)z * DM * DM;
    float* C = (z == 0) ? g_q : (z == 1) ? g_k : g_v;

    float acc[2][8][4] = {};
    gemm_mainloop(A, W, smf, sbase, brow, bcol, acc);

    int tid = threadIdx.x;
    int wid = tid >> 5, lane = tid & 31;
    int gid = lane >> 2, tig = lane & 3;
    int wm = wid >> 2, wn = wid & 3;

    if (z < 2) {
        // rope in registers: pair (acc[i][j], acc[i][j+4]) = dims (d, d+32)
#pragma unroll
        for (int i = 0; i < 2; i++) {
            int r0 = brow + wm * 32 + 16 * i + gid;
            float l0 = (float)(r0 & (LQ - 1));
            float l1 = (float)((r0 + 8) & (LQ - 1));
#pragma unroll
            for (int j = 0; j < 4; j++) {
                int d0 = 8 * j + 2 * tig;
                float if0 = __expf(ROPE_C * (float)d0);
                float if1 = __expf(ROPE_C * (float)(d0 + 1));
                float sn, cs;
                // (row r0, col d0)
                __sincosf(l0 * if0, &sn, &cs);
                float e = acc[i][j][0], o = acc[i][j + 4][0];
                acc[i][j][0]     = e * cs - o * sn;
                acc[i][j + 4][0] = e * sn + o * cs;
                // (row r0, col d0+1)
                __sincosf(l0 * if1, &sn, &cs);
                e = acc[i][j][1]; o = acc[i][j + 4][1];
                acc[i][j][1]     = e * cs - o * sn;
                acc[i][j + 4][1] = e * sn + o * cs;
                // (row r0+8, col d0)
                __sincosf(l1 * if0, &sn, &cs);
                e = acc[i][j][2]; o = acc[i][j + 4][2];
                acc[i][j][2]     = e * cs - o * sn;
                acc[i][j + 4][2] = e * sn + o * cs;
                // (row r0+8, col d0+1)
                __sincosf(l1 * if1, &sn, &cs);
                e = acc[i][j][3]; o = acc[i][j + 4][3];
                acc[i][j][3]     = e * cs - o * sn;
                acc[i][j + 4][3] = e * sn + o * cs;
            }
        }
    }

#pragma unroll
    for (int i = 0; i < 2; i++) {
        int r0 = brow + wm * 32 + 16 * i + gid;
        int r1 = r0 + 8;
#pragma unroll
        for (int j = 0; j < 8; j++) {
            int col = bcol + wn * 64 + 8 * j + 2 * tig;
            float c0 = acc[i][j][0], c1 = acc[i][j][1];
            float c2 = acc[i][j][2], c3 = acc[i][j][3];
            if (z < 2) {   // q/k feed mma downstream: keep tf32-exact
                c0 = rtf32(c0); c1 = rtf32(c1); c2 = rtf32(c2); c3 = rtf32(c3);
            }
            *(float2*)(C + (size_t)r0 * DM + col) = make_float2(c0, c1);
            *(float2*)(C + (size_t)r1 * DM + col) = make_float2(c2, c3);
        }
    }
}

// ---- generic GEMM with epilogues (Wout / Wgate) -----------------------------
// EPI: 1 = +bias then tf32-round store, 2 = gate mix.
template <int EPI>
__global__ __launch_bounds__(GT, 1) void mma_nt(const float* __restrict__ A,
                                                const float* __restrict__ W,
                                                float* __restrict__ C,
                                                const float* __restrict__ bias,
                                                const float* __restrict__ X1,
                                                const float* __restrict__ RES) {
    extern __shared__ float smf[];
    uint32_t sbase = smem_u32(smf);
    int brow = blockIdx.y * GBM;
    int bcol = blockIdx.x * GBN;

    float acc[2][8][4] = {};
    gemm_mainloop(A, W, smf, sbase, brow, bcol, acc);

    int tid = threadIdx.x;
    int wid = tid >> 5, lane = tid & 31;
    int gid = lane >> 2, tig = lane & 3;
    int wm = wid >> 2, wn = wid & 3;

#pragma unroll
    for (int i = 0; i < 2; i++) {
        int r0 = brow + wm * 32 + 16 * i + gid;
        int r1 = r0 + 8;
#pragma unroll
        for (int j = 0; j < 8; j++) {
            int col = bcol + wn * 64 + 8 * j + 2 * tig;
            float c0 = acc[i][j][0], c1 = acc[i][j][1];
            float c2 = acc[i][j][2], c3 = acc[i][j][3];
            float b0 = bias[col], b1 = bias[col + 1];
            c0 += b0; c1 += b1; c2 += b0; c3 += b1;
            size_t o0 = (size_t)r0 * DM + col;
            size_t o1 = (size_t)r1 * DM + col;
            if (EPI == 2) {
                float2 x0 = *(const float2*)(X1 + o0);
                float2 x1 = *(const float2*)(X1 + o1);
                float2 s0 = *(const float2*)(RES + o0);
                float2 s1 = *(const float2*)(RES + o1);
                float g0 = 1.f / (1.f + __expf(-c0));
                float g1 = 1.f / (1.f + __expf(-c1));
                float g2 = 1.f / (1.f + __expf(-c2));
                float g3 = 1.f / (1.f + __expf(-c3));
                c0 = g0 * x0.x + (1.f - g0) * s0.x;
                c1 = g1 * x0.y + (1.f - g1) * s0.y;
                c2 = g2 * x1.x + (1.f - g2) * s1.x;
                c3 = g3 * x1.y + (1.f - g3) * s1.y;
            }
            if (EPI == 1) {   // proj feeds the gate GEMM: keep it tf32-exact
                c0 = rtf32(c0); c1 = rtf32(c1); c2 = rtf32(c2); c3 = rtf32(c3);
            }
            *(float2*)(C + o0) = make_float2(c0, c1);
            *(float2*)(C + o1) = make_float2(c2, c3);
        }
    }
}

// ---------------- LayerNorm: one block per row (tf32-rounded output) ---------
__global__ __launch_bounds__(256) void ln_kernel(const float* __restrict__ dec,
                                                 const float* __restrict__ enc,
                                                 const float* __restrict__ gamma,
                                                 const float* __restrict__ beta) {
    int row = blockIdx.x;                // 0..8191
    const float* src;
    float* dst;
    if (row < MROWS) { src = dec + (size_t)row * DM; dst = g_qin + (size_t)row * DM; }
    else             { src = enc + (size_t)(row - MROWS) * DM; dst = g_kvin + (size_t)(row - MROWS) * DM; }
    int t = threadIdx.x;
    float4 x = ((const float4*)src)[t];
    float s  = x.x + x.y + x.z + x.w;
    float ss = x.x * x.x + x.y * x.y + x.z * x.z + x.w * x.w;
#pragma unroll
    for (int o = 16; o > 0; o >>= 1) {
        s  += __shfl_xor_sync(0xffffffffu, s, o);
        ss += __shfl_xor_sync(0xffffffffu, ss, o);
    }
    __shared__ float sb[16];
    int lane = t & 31, w = t >> 5;
    if (lane == 0) { sb[w] = s; sb[8 + w] = ss; }
    __syncthreads();
    float tot = 0.f, tot2 = 0.f;
#pragma unroll
    for (int i = 0; i < 8; i++) { tot += sb[i]; tot2 += sb[8 + i]; }
    float mean = tot * (1.0f / DM);
    float var  = tot2 * (1.0f / DM) - mean * mean;
    float inv  = rsqrtf(var + EPS);
    float4 g  = ((const float4*)gamma)[t];
    float4 bt = ((const float4*)beta)[t];
    float4 o4;
    o4.x = rtf32((x.x - mean) * inv * g.x + bt.x);
    o4.y = rtf32((x.y - mean) * inv * g.y + bt.y);
    o4.z = rtf32((x.z - mean) * inv * g.z + bt.z);
    o4.w = rtf32((x.w - mean) * inv * g.w + bt.w);
    ((float4*)dst)[t] = o4;
}

// ---------------- temporal bias, 128x128 base bilinear-resized to 512x512 ----
__device__ __forceinline__ float tb_base(int a, int b) {
    float d = fabsf((float)(a - b));
    return expf(-d * 0.1f) - d * 0.05f;
}

__global__ __launch_bounds__(256) void bias_kernel() {
    int idx = blockIdx.x * 256 + threadIdx.x;  // 512*512
    int i = idx >> 9, j = idx & 511;
    float yc = (i + 0.5f) * 0.25f - 0.5f;
    float xc = (j + 0.5f) * 0.25f - 0.5f;
    float y0f = floorf(yc), x0f = floorf(xc);
    float fy = yc - y0f, fx = xc - x0f;
    int y0 = min(max((int)y0f, 0), 127);
    int y1 = min(max((int)y0f + 1, 0), 127);
    int x0 = min(max((int)x0f, 0), 127);
    int x1 = min(max((int)x0f + 1, 0), 127);
    float v = (1.f - fy) * ((1.f - fx) * tb_base(y0, x0) + fx * tb_base(y0, x1)) +
              fy        * ((1.f - fx) * tb_base(y1, x0) + fx * tb_base(y1, x1));
    g_bias[idx] = v;
}

// ============== attention: flash-style with mma.sync tf32 ====================
// CTA: one (b,h) head, 64 q-rows. 128 threads, 4 warps (16 q-rows each).
// kv loop in 64-row tiles, double-buffered cp.async.
#define ATSTR 68
#define ATILE (64 * ATSTR)               // 4352 floats per 64x64 tile
#define ATT_SMEM (6 * ATILE * 4)         // Q + 2K + 2V + P = 104448 bytes

__global__ __launch_bounds__(128, 2) void attn_mma() {
    extern __shared__ float sm[];
    float* sQ = sm;                      // [64][68]
    float* sK = sm + ATILE;              // 2 stages
    float* sV = sm + 3 * ATILE;          // 2 stages
    float* sP = sm + 5 * ATILE;
    uint32_t sbase = smem_u32(sm);

    int bh = blockIdx.x, qt = blockIdx.y;
    int b = bh >> 4, h = bh & 15;
    int tid = threadIdx.x, wid = tid >> 5, lane = tid & 31;
    int gid = lane >> 2, tig = lane & 3;
    int mrow = wid * 16;

    const char* qg = (const char*)(g_q + ((size_t)(b * LQ + qt * 64)) * DM + h * HD);
#pragma unroll
    for (int j = 0; j < 8; j++) {
        int gi = tid + j * 128;
        int r = gi >> 4, g = gi & 15;
        cpasync16(sbase + (uint32_t)r * (ATSTR * 4) + g * 16,
                  qg + (size_t)r * (DM * 4) + g * 16);
    }
    auto load_kv = [&](int kt, int st) {
        const char* kg = (const char*)(g_k + ((size_t)(b * LQ + kt * 64)) * DM + h * HD);
        const char* vg = (const char*)(g_v + ((size_t)(b * LQ + kt * 64)) * DM + h * HD);
        uint32_t sk = sbase + (uint32_t)(1 + st) * ATILE * 4;
        uint32_t sv = sbase + (uint32_t)(3 + st) * ATILE * 4;
#pragma unroll
        for (int j = 0; j < 8; j++) {
            int gi = tid + j * 128;
            int r = gi >> 4, g = gi & 15;
            cpasync16(sk + (uint32_t)r * (ATSTR * 4) + g * 16, kg + (size_t)r * (DM * 4) + g * 16);
            cpasync16(sv + (uint32_t)r * (ATSTR * 4) + g * 16, vg + (size_t)r * (DM * 4) + g * 16);
        }
        CP_COMMIT();
    };
    load_kv(0, 0);

    float o[8][4] = {};
    float m0 = -1e30f, m1 = -1e30f, l0 = 0.f, l1 = 0.f;

    for (int kt = 0; kt < 8; kt++) {
        int st = kt & 1;
        if (kt < 7) {
            load_kv(kt + 1, st ^ 1);
            asm volatile("cp.async.wait_group 1;" ::: "memory");
        } else {
            asm volatile("cp.async.wait_group 0;" ::: "memory");
        }
        __syncthreads();

        const float* Kt = sK + st * ATILE;
        const float* Vt = sV + st * ATILE;

        uint32_t af[8][4];
        int ra = (mrow + gid) * ATSTR, rb = (mrow + gid + 8) * ATSTR;
#pragma unroll
        for (int ks = 0; ks < 8; ks++) {
            int col = ks * 8 + tig;
            af[ks][0] = __float_as_uint(sQ[ra + col]);
            af[ks][1] = __float_as_uint(sQ[rb + col]);
            af[ks][2] = __float_as_uint(sQ[ra + col + 4]);
            af[ks][3] = __float_as_uint(sQ[rb + col + 4]);
        }
        float s[8][4] = {};
#pragma unroll
        for (int nb = 0; nb < 8; nb++) {
            int n = (nb * 8 + gid) * ATSTR;
#pragma unroll
            for (int ks = 0; ks < 8; ks++) {
                int col = ks * 8 + tig;
                uint32_t bf[2];
                bf[0] = __float_as_uint(Kt[n + col]);
                bf[1] = __float_as_uint(Kt[n + col + 4]);
                mma8(s[nb], af[ks], bf);
            }
        }

        const float* bp = g_bias + (size_t)(qt * 64 + mrow + gid) * LQ + kt * 64;
        float nm0 = m0, nm1 = m1;
#pragma unroll
        for (int nb = 0; nb < 8; nb++) {
            int cc = nb * 8 + 2 * tig;
            float2 b0 = *(const float2*)(bp + cc);
            float2 b1 = *(const float2*)(bp + 8 * LQ + cc);
            s[nb][0] = s[nb][0] * ATT_SCALE + b0.x;
            s[nb][1] = s[nb][1] * ATT_SCALE + b0.y;
            s[nb][2] = s[nb][2] * ATT_SCALE + b1.x;
            s[nb][3] = s[nb][3] * ATT_SCALE + b1.y;
            nm0 = fmaxf(nm0, fmaxf(s[nb][0], s[nb][1]));
            nm1 = fmaxf(nm1, fmaxf(s[nb][2], s[nb][3]));
        }
        nm0 = fmaxf(nm0, __shfl_xor_sync(0xffffffffu, nm0, 1));
        nm0 = fmaxf(nm0, __shfl_xor_sync(0xffffffffu, nm0, 2));
        nm1 = fmaxf(nm1, __shfl_xor_sync(0xffffffffu, nm1, 1));
        nm1 = fmaxf(nm1, __shfl_xor_sync(0xffffffffu, nm1, 2));
        float al0 = __expf(m0 - nm0), al1 = __expf(m1 - nm1);
        m0 = nm0; m1 = nm1;
        float rs0 = 0.f, rs1 = 0.f;
#pragma unroll
        for (int nb = 0; nb < 8; nb++) {
            s[nb][0] = __expf(s[nb][0] - nm0);
            s[nb][1] = __expf(s[nb][1] - nm0);
            s[nb][2] = __expf(s[nb][2] - nm1);
            s[nb][3] = __expf(s[nb][3] - nm1);
            rs0 += s[nb][0] + s[nb][1];
            rs1 += s[nb][2] + s[nb][3];
        }
        rs0 += __shfl_xor_sync(0xffffffffu, rs0, 1);
        rs0 += __shfl_xor_sync(0xffffffffu, rs0, 2);
        rs1 += __shfl_xor_sync(0xffffffffu, rs1, 1);
        rs1 += __shfl_xor_sync(0xffffffffu, rs1, 2);
        l0 = l0 * al0 + rs0;
        l1 = l1 * al1 + rs1;
#pragma unroll
        for (int nb = 0; nb < 8; nb++) {
            o[nb][0] *= al0; o[nb][1] *= al0;
            o[nb][2] *= al1; o[nb][3] *= al1;
        }

#pragma unroll
        for (int nb = 0; nb < 8; nb++) {
            int cc = nb * 8 + 2 * tig;
            *(float2*)&sP[ra + cc] = make_float2(s[nb][0], s[nb][1]);
            *(float2*)&sP[rb + cc] = make_float2(s[nb][2], s[nb][3]);
        }
        __syncwarp();

        uint32_t pf[8][4];
#pragma unroll
        for (int ks = 0; ks < 8; ks++) {
            int col = ks * 8 + tig;
            pf[ks][0] = __float_as_uint(sP[ra + col]);
            pf[ks][1] = __float_as_uint(sP[rb + col]);
            pf[ks][2] = __float_as_uint(sP[ra + col + 4]);
            pf[ks][3] = __float_as_uint(sP[rb + col + 4]);
        }
#pragma unroll
        for (int nb = 0; nb < 8; nb++) {
            int n = nb * 8 + gid;
#pragma unroll
            for (int ks = 0; ks < 8; ks++) {
                uint32_t bf[2];
                bf[0] = __float_as_uint(Vt[(ks * 8 + tig) * ATSTR + n]);
                bf[1] = __float_as_uint(Vt[(ks * 8 + tig + 4) * ATSTR + n]);
                mma8(o[nb], pf[ks], bf);
            }
        }
        __syncthreads();
    }

    float i0 = 1.f / l0, i1 = 1.f / l1;
    float* og = g_att + ((size_t)(b * LQ + qt * 64 + mrow + gid)) * DM + h * HD;
#pragma unroll
    for (int nb = 0; nb < 8; nb++) {
        int cc = nb * 8 + 2 * tig;
        *(float2*)(og + cc) =
            make_float2(rtf32(o[nb][0] * i0), rtf32(o[nb][1] * i0));
        *(float2*)(og + (size_t)8 * DM + cc) =
            make_float2(rtf32(o[nb][2] * i1), rtf32(o[nb][3] * i1));
    }
}

// ---------------- launcher ---------------------------------------------------
extern "C" void kernel_launch(void* const* d_in, const int* in_sizes, int n_in,
                              void* d_out, int out_size) {
    const float* dec    = (const float*)d_in[0];
    const float* enc    = (const float*)d_in[1];
    const float* Wqkv   = (const float*)d_in[2];
    const float* Wout   = (const float*)d_in[3];
    const float* b_out  = (const float*)d_in[4];
    const float* Wgate  = (const float*)d_in[5];
    const float* b_gate = (const float*)d_in[6];
    const float* gamma  = (const float*)d_in[7];
    const float* beta   = (const float*)d_in[8];
    float* out = (float*)d_out;

    float *qin, *kvin, *att, *proj;
    cudaGetSymbolAddress((void**)&qin,   g_qin);
    cudaGetSymbolAddress((void**)&kvin,  g_kvin);
    cudaGetSymbolAddress((void**)&att,   g_att);
    cudaGetSymbolAddress((void**)&proj,  g_proj);

    cudaFuncSetAttribute(qkv_mma,   cudaFuncAttributeMaxDynamicSharedMemorySize, GEMM_SMEM);
    cudaFuncSetAttribute(mma_nt<1>, cudaFuncAttributeMaxDynamicSharedMemorySize, GEMM_SMEM);
    cudaFuncSetAttribute(mma_nt<2>, cudaFuncAttributeMaxDynamicSharedMemorySize, GEMM_SMEM);
    cudaFuncSetAttribute(attn_mma,  cudaFuncAttributeMaxDynamicSharedMemorySize, ATT_SMEM);

    ln_kernel<<<2 * MROWS, 256>>>(dec, enc, gamma, beta);
    bias_kernel<<<(LQ * LQ) / 256, 256>>>();

    qkv_mma<<<dim3(DM / GBN, MROWS / GBM, 3), GT, GEMM_SMEM>>>(Wqkv);

    attn_mma<<<dim3(NB * NH, LQ / 64), 128, ATT_SMEM>>>();

    dim3 gg(DM / GBN, MROWS / GBM);   // (4, 32) = 128 CTAs
    mma_nt<1><<<gg, GT, GEMM_SMEM>>>(att,  Wout,  proj, b_out,  nullptr, nullptr);
    mma_nt<2><<<gg, GT, GEMM_SMEM>>>(proj, Wgate, out,  b_gate, proj,    dec);
}

// round 14
// speedup vs baseline: 1.1096x; 1.1096x over previous
#include <cuda_runtime.h>
#include <math.h>
#include <stdint.h>

#define DM 1024
#define NH 16
#define HD 64
#define NB 8
#define LQ 512
#define MROWS 4096          // NB*LQ
#define ATT_SCALE 0.125f    // 64^-0.5
#define EPS 1e-5f
#define ROPE_C (-0.28782313662425576f)   // -ln(10000)/32

// ---------------- scratch (static device globals; no allocation) -------------
__device__ float g_qin[MROWS * DM];
__device__ float g_kvin[MROWS * DM];
__device__ float g_q[MROWS * DM];
__device__ float g_k[MROWS * DM];
__device__ float g_v[MROWS * DM];
__device__ float g_att[MROWS * DM];
__device__ float g_proj[MROWS * DM];
__device__ float g_bias[LQ * LQ];

// ---------------- helpers ----------------------------------------------------
__device__ __forceinline__ float rtf32(float x) {
    uint32_t r;
    asm("cvt.rna.tf32.f32 %0, %1;" : "=r"(r) : "f"(x));
    return __uint_as_float(r);
}
__device__ __forceinline__ uint32_t smem_u32(const void* p) {
    uint32_t a;
    asm("{ .reg .u64 t; cvta.to.shared.u64 t, %1; cvt.u32.u64 %0, t; }" : "=r"(a) : "l"(p));
    return a;
}
__device__ __forceinline__ void cpasync16(uint32_t s, const void* g) {
    asm volatile("cp.async.cg.shared.global [%0], [%1], 16;" :: "r"(s), "l"(g));
}
#define CP_COMMIT() asm volatile("cp.async.commit_group;" ::: "memory")

__device__ __forceinline__ void mma8(float* d, const uint32_t* a, const uint32_t* b) {
    asm volatile(
        "mma.sync.aligned.m16n8k8.row.col.f32.tf32.tf32.f32 "
        "{%0,%1,%2,%3}, {%4,%5,%6,%7}, {%8,%9}, {%0,%1,%2,%3};"
        : "+f"(d[0]), "+f"(d[1]), "+f"(d[2]), "+f"(d[3])
        : "r"(a[0]), "r"(a[1]), "r"(a[2]), "r"(a[3]), "r"(b[0]), "r"(b[1]));
}

// ======================= TF32 mma.sync GEMM core (8-warp, R9 config) =========
// C[M,N] = A[M,K=1024] * W[N,K=1024]^T ; CTA tile 128(M) x 256(N), BK=32.
// 8 warps (256 thr), 2(M) x 4(N) warp grid, warp tile 64x64, mma m16n8k8.
#define GBM 128
#define GBN 256
#define GBK 32
#define ASTR 36                          // smem row stride in floats (bank-CF)
#define A_SMF (GBM * ASTR)               // 4608 floats
#define B_SMF (GBN * ASTR)               // 9216 floats
#define STG_F (A_SMF + B_SMF)            // 13824 floats
#define STG_B (STG_F * 4)                // 55296 bytes
#define NSTG 3
#define NCHK (DM / GBK)                  // 32
#define GEMM_SMEM (NSTG * STG_B)         // 165888 bytes

__device__ __forceinline__ void gemm_mainloop(const float* __restrict__ A,
                                              const float* __restrict__ W,
                                              float* smf, uint32_t sbase,
                                              int brow, int bcol,
                                              float acc[4][8][4]) {
    int tid = threadIdx.x;
    int wid = tid >> 5, lane = tid & 31;
    int gid = lane >> 2, tig = lane & 3;
    int wm = wid >> 2, wn = wid & 3;

    const char* Arow = (const char*)(A + (size_t)brow * DM);
    const char* Wrow = (const char*)(W + (size_t)bcol * DM);

    auto load_chunk = [&](int c, int st) {
        uint32_t sA = sbase + st * STG_B;
        uint32_t sB = sA + A_SMF * 4;
        const char* Ag = Arow + (size_t)c * GBK * 4;
        const char* Bg = Wrow + (size_t)c * GBK * 4;
#pragma unroll
        for (int j = 0; j < 4; j++) {          // A: 1024 granules / 256 thr
            int gi = tid + j * 256;
            int r = gi >> 3, g = gi & 7;
            cpasync16(sA + r * 144 + g * 16, Ag + (size_t)r * (DM * 4) + g * 16);
        }
#pragma unroll
        for (int j = 0; j < 8; j++) {          // B: 2048 granules / 256 thr
            int gi = tid + j * 256;
            int r = gi >> 3, g = gi & 7;
            cpasync16(sB + r * 144 + g * 16, Bg + (size_t)r * (DM * 4) + g * 16);
        }
        CP_COMMIT();
    };

    load_chunk(0, 0);
    load_chunk(1, 1);

    for (int c = 0; c < NCHK; c++) {
        int st = c % NSTG;
        if (c + 2 < NCHK) load_chunk(c + 2, (c + 2) % NSTG);
        if (c < NCHK - 2)       asm volatile("cp.async.wait_group 2;" ::: "memory");
        else if (c == NCHK - 2) asm volatile("cp.async.wait_group 1;" ::: "memory");
        else                    asm volatile("cp.async.wait_group 0;" ::: "memory");
        __syncthreads();

        const float* sA = smf + st * STG_F;
        const float* sB = sA + A_SMF;
#pragma unroll
        for (int ks = 0; ks < 4; ks++) {
            int col = 8 * ks + tig;
            uint32_t af[4][4];
#pragma unroll
            for (int i = 0; i < 4; i++) {
                int m = wm * 64 + 16 * i + gid;
                af[i][0] = __float_as_uint(sA[m * ASTR + col]);
                af[i][1] = __float_as_uint(sA[(m + 8) * ASTR + col]);
                af[i][2] = __float_as_uint(sA[m * ASTR + col + 4]);
                af[i][3] = __float_as_uint(sA[(m + 8) * ASTR + col + 4]);
            }
            uint32_t bf[8][2];
#pragma unroll
            for (int j = 0; j < 8; j++) {
                int n = wn * 64 + 8 * j + gid;
                bf[j][0] = __float_as_uint(sB[n * ASTR + col]);
                bf[j][1] = __float_as_uint(sB[n * ASTR + col + 4]);
            }
#pragma unroll
            for (int i = 0; i < 4; i++)
#pragma unroll
                for (int j = 0; j < 8; j++) mma8(acc[i][j], af[i], bf[j]);
        }
        __syncthreads();
    }
}

// ---- fused QKV GEMM + RoPE epilogue -----------------------------------------
// z = blockIdx.z: 0 -> Q (rope), 1 -> K (rope), 2 -> V (plain).
__global__ __launch_bounds__(256, 1) void qkv_mma(const float* __restrict__ Wqkv) {
    extern __shared__ float smf[];
    uint32_t sbase = smem_u32(smf);
    int z = blockIdx.z;
    int brow = blockIdx.y * GBM;
    int bcol = blockIdx.x * GBN;

    const float* A = (z == 0) ? g_qin : g_kvin;
    const float* W = Wqkv + (size_t)z * DM * DM;
    float* C = (z == 0) ? g_q : (z == 1) ? g_k : g_v;

    float acc[4][8][4] = {};
    gemm_mainloop(A, W, smf, sbase, brow, bcol, acc);

    int tid = threadIdx.x;
    int wid = tid >> 5, lane = tid & 31;
    int gid = lane >> 2, tig = lane & 3;
    int wm = wid >> 2, wn = wid & 3;

    if (z < 2) {
        // rope in registers: pair (acc[i][j], acc[i][j+4]) = dims (d, d+32)
#pragma unroll
        for (int i = 0; i < 4; i++) {
            int r0 = brow + wm * 64 + 16 * i + gid;
            float l0 = (float)(r0 & (LQ - 1));
            float l1 = (float)((r0 + 8) & (LQ - 1));
#pragma unroll
            for (int j = 0; j < 4; j++) {
                int d0 = 8 * j + 2 * tig;
                float if0 = __expf(ROPE_C * (float)d0);
                float if1 = __expf(ROPE_C * (float)(d0 + 1));
                float sn, cs;
                __sincosf(l0 * if0, &sn, &cs);
                float e = acc[i][j][0], o = acc[i][j + 4][0];
                acc[i][j][0]     = e * cs - o * sn;
                acc[i][j + 4][0] = e * sn + o * cs;
                __sincosf(l0 * if1, &sn, &cs);
                e = acc[i][j][1]; o = acc[i][j + 4][1];
                acc[i][j][1]     = e * cs - o * sn;
                acc[i][j + 4][1] = e * sn + o * cs;
                __sincosf(l1 * if0, &sn, &cs);
                e = acc[i][j][2]; o = acc[i][j + 4][2];
                acc[i][j][2]     = e * cs - o * sn;
                acc[i][j + 4][2] = e * sn + o * cs;
                __sincosf(l1 * if1, &sn, &cs);
                e = acc[i][j][3]; o = acc[i][j + 4][3];
                acc[i][j][3]     = e * cs - o * sn;
                acc[i][j + 4][3] = e * sn + o * cs;
            }
        }
    }

#pragma unroll
    for (int i = 0; i < 4; i++) {
        int r0 = brow + wm * 64 + 16 * i + gid;
        int r1 = r0 + 8;
#pragma unroll
        for (int j = 0; j < 8; j++) {
            int col = bcol + wn * 64 + 8 * j + 2 * tig;
            float c0 = acc[i][j][0], c1 = acc[i][j][1];
            float c2 = acc[i][j][2], c3 = acc[i][j][3];
            if (z < 2) {   // q/k feed mma downstream: keep tf32-exact
                c0 = rtf32(c0); c1 = rtf32(c1); c2 = rtf32(c2); c3 = rtf32(c3);
            }
            *(float2*)(C + (size_t)r0 * DM + col) = make_float2(c0, c1);
            *(float2*)(C + (size_t)r1 * DM + col) = make_float2(c2, c3);
        }
    }
}

// ---- generic GEMM with epilogues (Wout / Wgate) -----------------------------
// EPI: 1 = +bias then tf32-round store, 2 = gate mix.
template <int EPI>
__global__ __launch_bounds__(256, 1) void mma_nt(const float* __restrict__ A,
                                                 const float* __restrict__ W,
                                                 float* __restrict__ C,
                                                 const float* __restrict__ bias,
                                                 const float* __restrict__ X1,
                                                 const float* __restrict__ RES) {
    extern __shared__ float smf[];
    uint32_t sbase = smem_u32(smf);
    int brow = blockIdx.y * GBM;
    int bcol = blockIdx.x * GBN;

    float acc[4][8][4] = {};
    gemm_mainloop(A, W, smf, sbase, brow, bcol, acc);

    int tid = threadIdx.x;
    int wid = tid >> 5, lane = tid & 31;
    int gid = lane >> 2, tig = lane & 3;
    int wm = wid >> 2, wn = wid & 3;

#pragma unroll
    for (int i = 0; i < 4; i++) {
        int r0 = brow + wm * 64 + 16 * i + gid;
        int r1 = r0 + 8;
#pragma unroll
        for (int j = 0; j < 8; j++) {
            int col = bcol + wn * 64 + 8 * j + 2 * tig;
            float c0 = acc[i][j][0], c1 = acc[i][j][1];
            float c2 = acc[i][j][2], c3 = acc[i][j][3];
            float b0 = bias[col], b1 = bias[col + 1];
            c0 += b0; c1 += b1; c2 += b0; c3 += b1;
            size_t o0 = (size_t)r0 * DM + col;
            size_t o1 = (size_t)r1 * DM + col;
            if (EPI == 2) {
                float2 x0 = *(const float2*)(X1 + o0);
                float2 x1 = *(const float2*)(X1 + o1);
                float2 s0 = *(const float2*)(RES + o0);
                float2 s1 = *(const float2*)(RES + o1);
                float g0 = 1.f / (1.f + __expf(-c0));
                float g1 = 1.f / (1.f + __expf(-c1));
                float g2 = 1.f / (1.f + __expf(-c2));
                float g3 = 1.f / (1.f + __expf(-c3));
                c0 = g0 * x0.x + (1.f - g0) * s0.x;
                c1 = g1 * x0.y + (1.f - g1) * s0.y;
                c2 = g2 * x1.x + (1.f - g2) * s1.x;
                c3 = g3 * x1.y + (1.f - g3) * s1.y;
            }
            if (EPI == 1) {
                c0 = rtf32(c0); c1 = rtf32(c1); c2 = rtf32(c2); c3 = rtf32(c3);
            }
            *(float2*)(C + o0) = make_float2(c0, c1);
            *(float2*)(C + o1) = make_float2(c2, c3);
        }
    }
}

// ---------------- LayerNorm: one block per row (tf32-rounded output) ---------
__global__ __launch_bounds__(256) void ln_kernel(const float* __restrict__ dec,
                                                 const float* __restrict__ enc,
                                                 const float* __restrict__ gamma,
                                                 const float* __restrict__ beta) {
    int row = blockIdx.x;                // 0..8191
    const float* src;
    float* dst;
    if (row < MROWS) { src = dec + (size_t)row * DM; dst = g_qin + (size_t)row * DM; }
    else             { src = enc + (size_t)(row - MROWS) * DM; dst = g_kvin + (size_t)(row - MROWS) * DM; }
    int t = threadIdx.x;
    float4 x = ((const float4*)src)[t];
    float s  = x.x + x.y + x.z + x.w;
    float ss = x.x * x.x + x.y * x.y + x.z * x.z + x.w * x.w;
#pragma unroll
    for (int o = 16; o > 0; o >>= 1) {
        s  += __shfl_xor_sync(0xffffffffu, s, o);
        ss += __shfl_xor_sync(0xffffffffu, ss, o);
    }
    __shared__ float sb[16];
    int lane = t & 31, w = t >> 5;
    if (lane == 0) { sb[w] = s; sb[8 + w] = ss; }
    __syncthreads();
    float tot = 0.f, tot2 = 0.f;
#pragma unroll
    for (int i = 0; i < 8; i++) { tot += sb[i]; tot2 += sb[8 + i]; }
    float mean = tot * (1.0f / DM);
    float var  = tot2 * (1.0f / DM) - mean * mean;
    float inv  = rsqrtf(var + EPS);
    float4 g  = ((const float4*)gamma)[t];
    float4 bt = ((const float4*)beta)[t];
    float4 o4;
    o4.x = rtf32((x.x - mean) * inv * g.x + bt.x);
    o4.y = rtf32((x.y - mean) * inv * g.y + bt.y);
    o4.z = rtf32((x.z - mean) * inv * g.z + bt.z);
    o4.w = rtf32((x.w - mean) * inv * g.w + bt.w);
    ((float4*)dst)[t] = o4;
}

// ---------------- temporal bias, 128x128 base bilinear-resized to 512x512 ----
__device__ __forceinline__ float tb_base(int a, int b) {
    float d = fabsf((float)(a - b));
    return expf(-d * 0.1f) - d * 0.05f;
}

__global__ __launch_bounds__(256) void bias_kernel() {
    int idx = blockIdx.x * 256 + threadIdx.x;  // 512*512
    int i = idx >> 9, j = idx & 511;
    float yc = (i + 0.5f) * 0.25f - 0.5f;
    float xc = (j + 0.5f) * 0.25f - 0.5f;
    float y0f = floorf(yc), x0f = floorf(xc);
    float fy = yc - y0f, fx = xc - x0f;
    int y0 = min(max((int)y0f, 0), 127);
    int y1 = min(max((int)y0f + 1, 0), 127);
    int x0 = min(max((int)x0f, 0), 127);
    int x1 = min(max((int)x0f + 1, 0), 127);
    float v = (1.f - fy) * ((1.f - fx) * tb_base(y0, x0) + fx * tb_base(y0, x1)) +
              fy        * ((1.f - fx) * tb_base(y1, x0) + fx * tb_base(y1, x1));
    g_bias[idx] = v;
}

// ============== attention: flash-style mma.sync tf32, 256 q-rows/CTA =========
// 8 warps (256 thr), each warp 32 q-rows x 64 kv. Q fragments hoisted to regs.
// K/V tiles double-buffered; V in stride-72 buffer (conflict-free fragments).
// P staged through the (retired) Q smem region, stride 68.
#define AQS 68
#define AVS 72
#define KTILE (64 * AQS)                 // 4352 floats
#define VTILE (64 * AVS)                 // 4608 floats
#define PQ_F (256 * AQS)                 // 17408 floats
#define ATT_SMEM ((PQ_F + 2 * KTILE + 2 * VTILE) * 4)   // 141312 bytes

__global__ __launch_bounds__(256, 1) void attn_mma() {
    extern __shared__ float sm[];
    float* sPQ = sm;                     // Q staging, then P
    float* sK  = sm + PQ_F;
    float* sV  = sK + 2 * KTILE;
    uint32_t sbase = smem_u32(sm);
    uint32_t sKb = sbase + PQ_F * 4;
    uint32_t sVb = sKb + 2 * KTILE * 4;

    int bh = blockIdx.x, qh = blockIdx.y;   // 128 heads x 2 q-halves
    int b = bh >> 4, h = bh & 15;
    int tid = threadIdx.x, wid = tid >> 5, lane = tid & 31;
    int gid = lane >> 2, tig = lane & 3;

    // ---- Q: 256 rows x 64 floats -> smem ------------------------------------
    const char* qg = (const char*)(g_q + ((size_t)(b * LQ + qh * 256)) * DM + h * HD);
#pragma unroll
    for (int j = 0; j < 16; j++) {
        int gi = tid + j * 256;
        int r = gi >> 4, g = gi & 15;
        cpasync16(sbase + (uint32_t)r * (AQS * 4) + g * 16,
                  qg + (size_t)r * (DM * 4) + g * 16);
    }
    CP_COMMIT();

    auto load_kv = [&](int kt, int st) {
        const char* kg = (const char*)(g_k + ((size_t)(b * LQ + kt * 64)) * DM + h * HD);
        const char* vg = (const char*)(g_v + ((size_t)(b * LQ + kt * 64)) * DM + h * HD);
#pragma unroll
        for (int j = 0; j < 4; j++) {
            int gi = tid + j * 256;
            int r = gi >> 4, g = gi & 15;
            cpasync16(sKb + (uint32_t)st * (KTILE * 4) + (uint32_t)r * (AQS * 4) + g * 16,
                      kg + (size_t)r * (DM * 4) + g * 16);
            cpasync16(sVb + (uint32_t)st * (VTILE * 4) + (uint32_t)r * (AVS * 4) + g * 16,
                      vg + (size_t)r * (DM * 4) + g * 16);
        }
        CP_COMMIT();
    };
    load_kv(0, 0);

    // Q done (kv0 may still be in flight)
    asm volatile("cp.async.wait_group 1;" ::: "memory");
    __syncthreads();

    // ---- hoist Q fragments to registers (reused across all kv tiles) --------
    uint32_t qf[2][8][4];
#pragma unroll
    for (int i = 0; i < 2; i++) {
        int ra = (wid * 32 + 16 * i + gid) * AQS;
        int rb = ra + 8 * AQS;
#pragma unroll
        for (int ks = 0; ks < 8; ks++) {
            int col = 8 * ks + tig;
            qf[i][ks][0] = __float_as_uint(sPQ[ra + col]);
            qf[i][ks][1] = __float_as_uint(sPQ[rb + col]);
            qf[i][ks][2] = __float_as_uint(sPQ[ra + col + 4]);
            qf[i][ks][3] = __float_as_uint(sPQ[rb + col + 4]);
        }
    }
    __syncthreads();   // all Q reads done before sPQ is reused for P

    float o[2][8][4] = {};
    float mx[2][2], ls[2][2];
#pragma unroll
    for (int i = 0; i < 2; i++) {
        mx[i][0] = -1e30f; mx[i][1] = -1e30f;
        ls[i][0] = 0.f;    ls[i][1] = 0.f;
    }

    for (int kt = 0; kt < 8; kt++) {
        int st = kt & 1;
        if (kt < 7) {
            load_kv(kt + 1, st ^ 1);
            asm volatile("cp.async.wait_group 1;" ::: "memory");
        } else {
            asm volatile("cp.async.wait_group 0;" ::: "memory");
        }
        __syncthreads();

        const float* Kt = sK + st * KTILE;
        const float* Vt = sV + st * VTILE;

        // ---- S = Q @ K^T ----------------------------------------------------
        float s[2][8][4] = {};
#pragma unroll
        for (int ks = 0; ks < 8; ks++) {
#pragma unroll
            for (int nb = 0; nb < 8; nb++) {
                uint32_t bf[2];
                int n = (nb * 8 + gid) * AQS + 8 * ks + tig;
                bf[0] = __float_as_uint(Kt[n]);
                bf[1] = __float_as_uint(Kt[n + 4]);
                mma8(s[0][nb], qf[0][ks], bf);
                mma8(s[1][nb], qf[1][ks], bf);
            }
        }

        // ---- scale + bias + online softmax (per i-block) --------------------
#pragma unroll
        for (int i = 0; i < 2; i++) {
            int qrow = qh * 256 + wid * 32 + 16 * i + gid;
            const float* bp = g_bias + (size_t)qrow * LQ + kt * 64;
            float nm0 = mx[i][0], nm1 = mx[i][1];
#pragma unroll
            for (int nb = 0; nb < 8; nb++) {
                int cc = nb * 8 + 2 * tig;
                float2 b0 = *(const float2*)(bp + cc);
                float2 b1 = *(const float2*)(bp + 8 * LQ + cc);
                s[i][nb][0] = s[i][nb][0] * ATT_SCALE + b0.x;
                s[i][nb][1] = s[i][nb][1] * ATT_SCALE + b0.y;
                s[i][nb][2] = s[i][nb][2] * ATT_SCALE + b1.x;
                s[i][nb][3] = s[i][nb][3] * ATT_SCALE + b1.y;
                nm0 = fmaxf(nm0, fmaxf(s[i][nb][0], s[i][nb][1]));
                nm1 = fmaxf(nm1, fmaxf(s[i][nb][2], s[i][nb][3]));
            }
            nm0 = fmaxf(nm0, __shfl_xor_sync(0xffffffffu, nm0, 1));
            nm0 = fmaxf(nm0, __shfl_xor_sync(0xffffffffu, nm0, 2));
            nm1 = fmaxf(nm1, __shfl_xor_sync(0xffffffffu, nm1, 1));
            nm1 = fmaxf(nm1, __shfl_xor_sync(0xffffffffu, nm1, 2));
            float al0 = __expf(mx[i][0] - nm0), al1 = __expf(mx[i][1] - nm1);
            mx[i][0] = nm0; mx[i][1] = nm1;
            float rs0 = 0.f, rs1 = 0.f;
#pragma unroll
            for (int nb = 0; nb < 8; nb++) {
                s[i][nb][0] = __expf(s[i][nb][0] - nm0);
                s[i][nb][1] = __expf(s[i][nb][1] - nm0);
                s[i][nb][2] = __expf(s[i][nb][2] - nm1);
                s[i][nb][3] = __expf(s[i][nb][3] - nm1);
                rs0 += s[i][nb][0] + s[i][nb][1];
                rs1 += s[i][nb][2] + s[i][nb][3];
            }
            rs0 += __shfl_xor_sync(0xffffffffu, rs0, 1);
            rs0 += __shfl_xor_sync(0xffffffffu, rs0, 2);
            rs1 += __shfl_xor_sync(0xffffffffu, rs1, 1);
            rs1 += __shfl_xor_sync(0xffffffffu, rs1, 2);
            ls[i][0] = ls[i][0] * al0 + rs0;
            ls[i][1] = ls[i][1] * al1 + rs1;
#pragma unroll
            for (int nb = 0; nb < 8; nb++) {
                o[i][nb][0] *= al0; o[i][nb][1] *= al0;
                o[i][nb][2] *= al1; o[i][nb][3] *= al1;
            }
            // P -> smem (warp-private rows)
            int ra = (wid * 32 + 16 * i + gid) * AQS;
            int rb = ra + 8 * AQS;
#pragma unroll
            for (int nb = 0; nb < 8; nb++) {
                int cc = nb * 8 + 2 * tig;
                *(float2*)&sPQ[ra + cc] = make_float2(s[i][nb][0], s[i][nb][1]);
                *(float2*)&sPQ[rb + cc] = make_float2(s[i][nb][2], s[i][nb][3]);
            }
        }
        __syncwarp();

        // ---- O += P @ V -----------------------------------------------------
#pragma unroll
        for (int ks = 0; ks < 8; ks++) {
            uint32_t pf[2][4];
#pragma unroll
            for (int i = 0; i < 2; i++) {
                int ra = (wid * 32 + 16 * i + gid) * AQS;
                int rb = ra + 8 * AQS;
                int col = 8 * ks + tig;
                pf[i][0] = __float_as_uint(sPQ[ra + col]);
                pf[i][1] = __float_as_uint(sPQ[rb + col]);
                pf[i][2] = __float_as_uint(sPQ[ra + col + 4]);
                pf[i][3] = __float_as_uint(sPQ[rb + col + 4]);
            }
#pragma unroll
            for (int nb = 0; nb < 8; nb++) {
                uint32_t bf[2];
                bf[0] = __float_as_uint(Vt[(8 * ks + tig) * AVS + 8 * nb + gid]);
                bf[1] = __float_as_uint(Vt[(8 * ks + tig + 4) * AVS + 8 * nb + gid]);
                mma8(o[0][nb], pf[0], bf);
                mma8(o[1][nb], pf[1], bf);
            }
        }
        __syncthreads();   // tile fully consumed before next prefetch overwrite
    }

    // ---- epilogue -----------------------------------------------------------
#pragma unroll
    for (int i = 0; i < 2; i++) {
        float i0 = 1.f / ls[i][0], i1 = 1.f / ls[i][1];
        float* og = g_att + ((size_t)(b * LQ + qh * 256 + wid * 32 + 16 * i + gid)) * DM + h * HD;
#pragma unroll
        for (int nb = 0; nb < 8; nb++) {
            int cc = nb * 8 + 2 * tig;
            *(float2*)(og + cc) =
                make_float2(rtf32(o[i][nb][0] * i0), rtf32(o[i][nb][1] * i0));
            *(float2*)(og + (size_t)8 * DM + cc) =
                make_float2(rtf32(o[i][nb][2] * i1), rtf32(o[i][nb][3] * i1));
        }
    }
}

// ---------------- launcher ---------------------------------------------------
extern "C" void kernel_launch(void* const* d_in, const int* in_sizes, int n_in,
                              void* d_out, int out_size) {
    const float* dec    = (const float*)d_in[0];
    const float* enc    = (const float*)d_in[1];
    const float* Wqkv   = (const float*)d_in[2];
    const float* Wout   = (const float*)d_in[3];
    const float* b_out  = (const float*)d_in[4];
    const float* Wgate  = (const float*)d_in[5];
    const float* b_gate = (const float*)d_in[6];
    const float* gamma  = (const float*)d_in[7];
    const float* beta   = (const float*)d_in[8];
    float* out = (float*)d_out;

    float *att, *proj;
    cudaGetSymbolAddress((void**)&att,  g_att);
    cudaGetSymbolAddress((void**)&proj, g_proj);

    cudaFuncSetAttribute(qkv_mma,   cudaFuncAttributeMaxDynamicSharedMemorySize, GEMM_SMEM);
    cudaFuncSetAttribute(mma_nt<1>, cudaFuncAttributeMaxDynamicSharedMemorySize, GEMM_SMEM);
    cudaFuncSetAttribute(mma_nt<2>, cudaFuncAttributeMaxDynamicSharedMemorySize, GEMM_SMEM);
    cudaFuncSetAttribute(attn_mma,  cudaFuncAttributeMaxDynamicSharedMemorySize, ATT_SMEM);

    ln_kernel<<<2 * MROWS, 256>>>(dec, enc, gamma, beta);
    bias_kernel<<<(LQ * LQ) / 256, 256>>>();

    qkv_mma<<<dim3(DM / GBN, MROWS / GBM, 3), 256, GEMM_SMEM>>>(Wqkv);

    attn_mma<<<dim3(NB * NH, 2), 256, ATT_SMEM>>>();

    dim3 gg(DM / GBN, MROWS / GBM);   // (4, 32) = 128 CTAs
    mma_nt<1><<<gg, 256, GEMM_SMEM>>>(att,  Wout,  proj, b_out,  nullptr, nullptr);
    mma_nt<2><<<gg, 256, GEMM_SMEM>>>(proj, Wgate, out,  b_gate, proj,    dec);
}